// round 5
// baseline (speedup 1.0000x reference)
#include <cuda_runtime.h>

#define MM 8192
#define KMAX 16
#define NROWCHUNK 64
#define ROWS_PER_CHUNK (MM / NROWCHUNK)   // 128
#define NCOLTILE 16
#define COLS_PER_TILE (MM / NCOLTILE)     // 512 (128 threads x float4)

#define DMF   ((float)(0.9 / 8192.0))               // DELTA_M as f32
#define CGAM  ((float)(1.0 / (1.0 - 0.45 + 1e-12))) // 1/(M_MAX-M_MIN+EPS) as f32
#define COEF2DM ((float)(2.0 * 0.9 / 8192.0))       // 2*DELTA_M as f32

// ---------------- device state (no allocations allowed) ----------------
__device__ __align__(16) float d_n[MM];
__device__ __align__(16) float d_ntmp[MM];
__device__ __align__(16) float d_v[MM];
__device__ __align__(16) float d_G[MM];
__device__ __align__(16) float4 d_part4[NROWCHUNK * MM / 4];  // 2 MB
__device__ float d_S;      // S_hat
__device__ int   d_N;
__device__ float d_h, d_h2, d_h6;

// ---------------- init: copy state; compute N,h exactly like _num_substeps (f64) ----
__global__ void k_init(const float* __restrict__ x, const float* __restrict__ m) {
    const int t = threadIdx.x;
    for (int i = t; i < MM; i += 256) d_n[i] = x[i];

    __shared__ double sred[256];
    const double S_hat = (double)x[MM];
    const double S     = 10.0 * S_hat;
    const double alpha = 0.8 * S / (2.0 + S + 1e-12);
    const double csub  = 1.0 / (1.0 - 0.45 + 1e-12);

    double lmax = 0.0;
    for (int i = t; i < MM; i += 256) {
        double md = (double)m[i];
        double g  = 1.0 / (1.0 - md + 1e-12) - csub;
        if (g < 0.0) g = 0.0;
        double G = g * (alpha * md);
        if (G > lmax) lmax = G;
    }
    sred[t] = lmax;
    __syncthreads();
    for (int s = 128; s > 0; s >>= 1) {
        if (t < s) sred[t] = fmax(sred[t], sred[t + s]);
        __syncthreads();
    }
    if (t == 0) {
        d_S = x[MM];
        const double vmax = fabs(alpha) * (double)m[MM - 1];
        const double dm   = 0.9 / 8192.0;
        const double cfl  = vmax * 0.002 / (dm + 1e-12);
        int Ncfl = (vmax == 0.0 || cfl <= 0.8) ? 1 : (int)ceil(cfl / 0.8);
        const double rr = sred[0] * 0.002;
        int Nre = (sred[0] == 0.0 || rr <= 0.5) ? 1 : (int)ceil(rr / 0.5);
        int N = Ncfl > Nre ? Ncfl : Nre;
        if (N < 1) N = 1;
        if (N > KMAX) N = KMAX;   // provably never triggers (N<=14)
        d_N = N;
        double h = 0.002 / (double)N;
        d_h  = (float)h;
        d_h2 = (float)(0.5 * h);
        d_h6 = (float)(h / 6.0);
    }
}

// ---------------- per-substep: RK4 transport + G/v/uptake/S update (1 block) ----------
__global__ __launch_bounds__(1024, 1)
void k_transport(const float* __restrict__ m, int step) {
    if (step >= d_N) return;

    __shared__ float sa[MM];       // RK4 stage input
    __shared__ float sred[1024];   // uptake reduction

    const int t    = threadIdx.x;
    const int base = t * 8;
    const float invDM = 1.0f / DMF;

    const float Sh = d_S;                     // S_hat
    const float S  = 10.0f * Sh;              // S = S_MAX * S_hat   <-- THE FIX
    const float h  = d_h;
    const float h2 = d_h2;
    const float h6 = d_h6;
    const float alphaT = 0.8f * S / (2.0f + S);            // transport alpha (no EPS)
    const float alphaE = 0.8f * S / (2.0f + S + 1e-12f);   // _r_g alpha (with EPS)

    float rn[8], rm[8], racc[8], rk[8];
    float rmL = (base > 0) ? m[base - 1] : 0.0f;
    #pragma unroll
    for (int e = 0; e < 8; e++) {
        rn[e] = d_n[base + e];
        rm[e] = m[base + e];
        sa[base + e] = rn[e];
        racc[e] = 0.0f;
    }
    __syncthreads();

    // one RK4 stage: rk[] = T(sa)
    #define STAGE()                                                              \
        _Pragma("unroll")                                                        \
        for (int e = 0; e < 8; e++) {                                            \
            const int i = base + e;                                              \
            const float ri = alphaT * rm[e] * sa[i];                             \
            float k;                                                             \
            if (i == 0) {                                                        \
                k = -ri * invDM;                                                 \
            } else {                                                             \
                const float mp = (e > 0) ? rm[e - 1] : rmL;                      \
                const float rim1 = alphaT * mp * sa[i - 1];                      \
                k = (i == MM - 1) ? (rim1 + ri) * invDM                          \
                                  : -(ri - rim1) * invDM;                        \
            }                                                                    \
            rk[e] = k;                                                           \
        }

    // k1
    STAGE();
    __syncthreads();
    #pragma unroll
    for (int e = 0; e < 8; e++) { racc[e] += rk[e]; sa[base + e] = rn[e] + h2 * rk[e]; }
    __syncthreads();
    // k2
    STAGE();
    __syncthreads();
    #pragma unroll
    for (int e = 0; e < 8; e++) { racc[e] += 2.0f * rk[e]; sa[base + e] = rn[e] + h2 * rk[e]; }
    __syncthreads();
    // k3
    STAGE();
    __syncthreads();
    #pragma unroll
    for (int e = 0; e < 8; e++) { racc[e] += 2.0f * rk[e]; sa[base + e] = rn[e] + h * rk[e]; }
    __syncthreads();
    // k4
    STAGE();
    #pragma unroll
    for (int e = 0; e < 8; e++) racc[e] += rk[e];
    #undef STAGE

    // n_tmp, G, v, uptake
    float upt = 0.0f;
    #pragma unroll
    for (int e = 0; e < 8; e++) {
        const int i = base + e;
        const float ntmp = rn[e] + h6 * racc[e];
        const float rg   = alphaE * rm[e];
        float gm = 1.0f / (1.0f - rm[e] + 1e-12f) - CGAM;
        if (gm < 0.0f) gm = 0.0f;
        const float G = gm * rg;
        d_ntmp[i] = ntmp;
        d_G[i]    = G;
        d_v[i]    = G * ntmp;
        upt += rg * ntmp;
    }
    sred[t] = upt;
    __syncthreads();
    for (int s = 512; s > 0; s >>= 1) {
        if (t < s) sred[t] += sred[t + s];
        __syncthreads();
    }
    if (t == 0) {
        const float uptake = sred[0] * DMF;
        const float Sn = Sh + h * (-0.1f * uptake);   // KAPPA = 0.1
        d_S = fmaxf(Sn, 0.0f);
    }
}

// ---------------- matvec partials: result[j] = sum_i v[i] * P[i,j] ----------------
__global__ __launch_bounds__(128)
void k_matvec(const float* __restrict__ P, int step) {
    if (step >= d_N) return;
    __shared__ float sv[ROWS_PER_CHUNK];
    const int t  = threadIdx.x;                 // 0..127
    const int ct = blockIdx.x;                  // column tile
    const int rc = blockIdx.y;                  // row chunk
    const int r0 = rc * ROWS_PER_CHUNK;

    if (t < ROWS_PER_CHUNK) sv[t] = d_v[r0 + t];
    __syncthreads();

    const int j = ct * COLS_PER_TILE + t * 4;
    const float4* Pr = (const float4*)(P + (size_t)r0 * MM + j);
    float4 acc = make_float4(0.f, 0.f, 0.f, 0.f);
    #pragma unroll 8
    for (int i = 0; i < ROWS_PER_CHUNK; i++) {
        const float  vi = sv[i];
        const float4 p  = Pr[(size_t)i * (MM / 4)];
        acc.x += vi * p.x; acc.y += vi * p.y;
        acc.z += vi * p.z; acc.w += vi * p.w;
    }
    d_part4[(size_t)rc * (MM / 4) + (j >> 2)] = acc;
}

// ---------------- deterministic reduce + implicit reaction update ----------------
__global__ void k_update(int step) {
    if (step >= d_N) return;
    const int j = blockIdx.x * blockDim.x + threadIdx.x;
    const float* part = (const float*)d_part4;
    float s = 0.0f;
    #pragma unroll
    for (int c = 0; c < NROWCHUNK; c++) s += part[c * MM + j];
    const float gain = COEF2DM * s;
    const float h = d_h;
    const float nn = (d_ntmp[j] + h * gain) / (1.0f + h * d_G[j]);
    d_n[j] = fmaxf(nn, 0.0f);
}

// ---------------- output ----------------
__global__ void k_final(float* __restrict__ out) {
    const int j = blockIdx.x * blockDim.x + threadIdx.x;
    if (j < MM) out[j] = d_n[j];
    if (j == 0) out[MM] = d_S;
}

extern "C" void kernel_launch(void* const* d_in, const int* in_sizes, int n_in,
                              void* d_out, int out_size) {
    const float* x = nullptr;
    const float* m = nullptr;
    const float* P = nullptr;
    for (int i = 0; i < n_in; i++) {
        if (in_sizes[i] == MM + 1)       x = (const float*)d_in[i];
        else if (in_sizes[i] == MM)      m = (const float*)d_in[i];
        else if (in_sizes[i] == MM * MM) P = (const float*)d_in[i];
    }
    float* out = (float*)d_out;

    k_init<<<1, 256>>>(x, m);
    for (int s = 0; s < KMAX; s++) {
        k_transport<<<1, 1024>>>(m, s);
        k_matvec<<<dim3(NCOLTILE, NROWCHUNK), 128>>>(P, s);
        k_update<<<MM / 128, 128>>>(s);
    }
    k_final<<<(MM + 128) / 128, 128>>>(out);
}

// round 6
// speedup vs baseline: 1.0055x; 1.0055x over previous
#include <cuda_runtime.h>

#define MM 8192
#define KMAX 14
#define NROWCHUNK 64
#define ROWS_PER_CHUNK (MM / NROWCHUNK)   // 128
#define NCOLTILE 16
#define COLS_PER_TILE (MM / NCOLTILE)     // 512 (128 threads x float4)

#define DMF   ((float)(0.9 / 8192.0))               // DELTA_M as f32
#define CGAM  ((float)(1.0 / (1.0 - 0.45 + 1e-12))) // 1/(M_MAX-M_MIN+EPS) as f32
#define COEF2DM ((float)(2.0 * 0.9 / 8192.0))       // 2*DELTA_M as f32

// ---------------- device state (no allocations allowed) ----------------
__device__ __align__(16) float d_n[MM];
__device__ __align__(16) float d_ntmp[MM];
__device__ __align__(16) float d_v[MM];
__device__ __align__(16) float d_G[MM];
__device__ __align__(16) float4 d_part4[NROWCHUNK * MM / 4];  // 2 MB
__device__ float d_S;      // S_hat
__device__ int   d_N;
__device__ float d_h, d_h2, d_h6;

// ---------------- init: copy state; compute N,h exactly like _num_substeps (f64) ----
__global__ void k_init(const float* __restrict__ x, const float* __restrict__ m) {
    const int t = threadIdx.x;
    for (int i = t; i < MM; i += 256) d_n[i] = x[i];

    __shared__ double sred[256];
    const double S_hat = (double)x[MM];
    const double S     = 10.0 * S_hat;
    const double alpha = 0.8 * S / (2.0 + S + 1e-12);
    const double csub  = 1.0 / (1.0 - 0.45 + 1e-12);

    double lmax = 0.0;
    for (int i = t; i < MM; i += 256) {
        double md = (double)m[i];
        double g  = 1.0 / (1.0 - md + 1e-12) - csub;
        if (g < 0.0) g = 0.0;
        double G = g * (alpha * md);
        if (G > lmax) lmax = G;
    }
    sred[t] = lmax;
    __syncthreads();
    for (int s = 128; s > 0; s >>= 1) {
        if (t < s) sred[t] = fmax(sred[t], sred[t + s]);
        __syncthreads();
    }
    if (t == 0) {
        d_S = x[MM];
        const double vmax = fabs(alpha) * (double)m[MM - 1];
        const double dm   = 0.9 / 8192.0;
        const double cfl  = vmax * 0.002 / (dm + 1e-12);
        int Ncfl = (vmax == 0.0 || cfl <= 0.8) ? 1 : (int)ceil(cfl / 0.8);
        const double rr = sred[0] * 0.002;
        int Nre = (sred[0] == 0.0 || rr <= 0.5) ? 1 : (int)ceil(rr / 0.5);
        int N = Ncfl > Nre ? Ncfl : Nre;
        if (N < 1) N = 1;
        if (N > KMAX) N = KMAX;   // provably never triggers (N<=14)
        d_N = N;
        double h = 0.002 / (double)N;
        d_h  = (float)h;
        d_h2 = (float)(0.5 * h);
        d_h6 = (float)(h / 6.0);
    }
}

// ---------------- per-substep: RK4 transport + G/v/uptake/S update (1 block) ----------
__global__ __launch_bounds__(1024, 1)
void k_transport(const float* __restrict__ m, int step) {
    if (step >= d_N) return;

    __shared__ float sa[MM];       // RK4 stage input
    __shared__ float sred[1024];   // uptake reduction

    const int t    = threadIdx.x;
    const int base = t * 8;
    const float invDM = 1.0f / DMF;

    const float Sh = d_S;                     // S_hat
    const float S  = 10.0f * Sh;              // S = S_MAX * S_hat
    const float h  = d_h;
    const float h2 = d_h2;
    const float h6 = d_h6;
    const float alphaT = 0.8f * S / (2.0f + S);            // transport alpha (no EPS)
    const float alphaE = 0.8f * S / (2.0f + S + 1e-12f);   // _r_g alpha (with EPS)

    float rn[8], rm[8], racc[8], rk[8];
    float rmL = (base > 0) ? m[base - 1] : 0.0f;
    #pragma unroll
    for (int e = 0; e < 8; e++) {
        rn[e] = d_n[base + e];
        rm[e] = m[base + e];
        sa[base + e] = rn[e];
        racc[e] = 0.0f;
    }
    __syncthreads();

    // one RK4 stage: rk[] = T(sa)
    #define STAGE()                                                              \
        _Pragma("unroll")                                                        \
        for (int e = 0; e < 8; e++) {                                            \
            const int i = base + e;                                              \
            const float ri = alphaT * rm[e] * sa[i];                             \
            float k;                                                             \
            if (i == 0) {                                                        \
                k = -ri * invDM;                                                 \
            } else {                                                             \
                const float mp = (e > 0) ? rm[e - 1] : rmL;                      \
                const float rim1 = alphaT * mp * sa[i - 1];                      \
                k = (i == MM - 1) ? (rim1 + ri) * invDM                          \
                                  : -(ri - rim1) * invDM;                        \
            }                                                                    \
            rk[e] = k;                                                           \
        }

    // k1
    STAGE();
    __syncthreads();
    #pragma unroll
    for (int e = 0; e < 8; e++) { racc[e] += rk[e]; sa[base + e] = rn[e] + h2 * rk[e]; }
    __syncthreads();
    // k2
    STAGE();
    __syncthreads();
    #pragma unroll
    for (int e = 0; e < 8; e++) { racc[e] += 2.0f * rk[e]; sa[base + e] = rn[e] + h2 * rk[e]; }
    __syncthreads();
    // k3
    STAGE();
    __syncthreads();
    #pragma unroll
    for (int e = 0; e < 8; e++) { racc[e] += 2.0f * rk[e]; sa[base + e] = rn[e] + h * rk[e]; }
    __syncthreads();
    // k4
    STAGE();
    #pragma unroll
    for (int e = 0; e < 8; e++) racc[e] += rk[e];
    #undef STAGE

    // n_tmp, G, v, uptake
    float upt = 0.0f;
    #pragma unroll
    for (int e = 0; e < 8; e++) {
        const int i = base + e;
        const float ntmp = rn[e] + h6 * racc[e];
        const float rg   = alphaE * rm[e];
        float gm = 1.0f / (1.0f - rm[e] + 1e-12f) - CGAM;
        if (gm < 0.0f) gm = 0.0f;
        const float G = gm * rg;
        d_ntmp[i] = ntmp;
        d_G[i]    = G;
        d_v[i]    = G * ntmp;
        upt += rg * ntmp;
    }
    sred[t] = upt;
    __syncthreads();
    for (int s = 512; s > 0; s >>= 1) {
        if (t < s) sred[t] += sred[t + s];
        __syncthreads();
    }
    if (t == 0) {
        const float uptake = sred[0] * DMF;
        const float Sn = Sh + h * (-0.1f * uptake);   // KAPPA = 0.1
        d_S = fmaxf(Sn, 0.0f);
    }
}

// ---------------- matvec partials: result[j] = sum_i v[i] * P[i,j] ----------------
__global__ __launch_bounds__(128)
void k_matvec(const float* __restrict__ P, int step) {
    if (step >= d_N) return;
    __shared__ float sv[ROWS_PER_CHUNK];
    const int t  = threadIdx.x;                 // 0..127
    const int ct = blockIdx.x;                  // column tile
    const int rc = blockIdx.y;                  // row chunk
    const int r0 = rc * ROWS_PER_CHUNK;

    if (t < ROWS_PER_CHUNK) sv[t] = d_v[r0 + t];
    __syncthreads();

    const int j = ct * COLS_PER_TILE + t * 4;
    const float4* Pr = (const float4*)(P + (size_t)r0 * MM + j);
    float4 acc = make_float4(0.f, 0.f, 0.f, 0.f);
    #pragma unroll 8
    for (int i = 0; i < ROWS_PER_CHUNK; i++) {
        const float  vi = sv[i];
        const float4 p  = Pr[(size_t)i * (MM / 4)];
        acc.x += vi * p.x; acc.y += vi * p.y;
        acc.z += vi * p.z; acc.w += vi * p.w;
    }
    d_part4[(size_t)rc * (MM / 4) + (j >> 2)] = acc;
}

// ---------------- fast deterministic reduce + implicit reaction update ----------------
// 64 blocks x 128 threads. Block handles 32 float4-columns (128 j).
// Thread (j4, cg): sums partials c in [cg*16, cg*16+16) as float4 (coalesced, L2-hot).
// Fixed combine order cg0+cg1+cg2+cg3 -> deterministic.
__global__ __launch_bounds__(128)
void k_update(int step) {
    if (step >= d_N) return;
    __shared__ float4 sp[128];
    const int t  = threadIdx.x;
    const int jl = t & 31;                       // local j4 index 0..31
    const int cg = t >> 5;                       // c-group 0..3
    const int j4 = blockIdx.x * 32 + jl;         // global float4 column

    float4 a = make_float4(0.f, 0.f, 0.f, 0.f);
    const int c0 = cg * (NROWCHUNK / 4);
    #pragma unroll
    for (int c = 0; c < NROWCHUNK / 4; c++) {
        const float4 p = d_part4[(size_t)(c0 + c) * (MM / 4) + j4];
        a.x += p.x; a.y += p.y; a.z += p.z; a.w += p.w;
    }
    sp[t] = a;
    __syncthreads();

    if (cg == 0) {
        const float4 b1 = sp[32 + jl];
        const float4 b2 = sp[64 + jl];
        const float4 b3 = sp[96 + jl];
        a = sp[jl];
        a.x += b1.x; a.y += b1.y; a.z += b1.z; a.w += b1.w;
        a.x += b2.x; a.y += b2.y; a.z += b2.z; a.w += b2.w;
        a.x += b3.x; a.y += b3.y; a.z += b3.z; a.w += b3.w;

        const float h = d_h;
        const float4 nt = ((const float4*)d_ntmp)[j4];
        const float4 Gg = ((const float4*)d_G)[j4];
        float4 nn;
        nn.x = fmaxf((nt.x + h * (COEF2DM * a.x)) / (1.0f + h * Gg.x), 0.0f);
        nn.y = fmaxf((nt.y + h * (COEF2DM * a.y)) / (1.0f + h * Gg.y), 0.0f);
        nn.z = fmaxf((nt.z + h * (COEF2DM * a.z)) / (1.0f + h * Gg.z), 0.0f);
        nn.w = fmaxf((nt.w + h * (COEF2DM * a.w)) / (1.0f + h * Gg.w), 0.0f);
        ((float4*)d_n)[j4] = nn;
    }
}

// ---------------- output ----------------
__global__ void k_final(float* __restrict__ out) {
    const int j = blockIdx.x * blockDim.x + threadIdx.x;
    if (j < MM) out[j] = d_n[j];
    if (j == 0) out[MM] = d_S;
}

extern "C" void kernel_launch(void* const* d_in, const int* in_sizes, int n_in,
                              void* d_out, int out_size) {
    const float* x = nullptr;
    const float* m = nullptr;
    const float* P = nullptr;
    for (int i = 0; i < n_in; i++) {
        if (in_sizes[i] == MM + 1)       x = (const float*)d_in[i];
        else if (in_sizes[i] == MM)      m = (const float*)d_in[i];
        else if (in_sizes[i] == MM * MM) P = (const float*)d_in[i];
    }
    float* out = (float*)d_out;

    k_init<<<1, 256>>>(x, m);
    for (int s = 0; s < KMAX; s++) {
        k_transport<<<1, 1024>>>(m, s);
        k_matvec<<<dim3(NCOLTILE, NROWCHUNK), 128>>>(P, s);
        k_update<<<MM / 128, 128>>>(s);
    }
    k_final<<<(MM + 128) / 128, 128>>>(out);
}